// round 14
// baseline (speedup 1.0000x reference)
#include <cuda_runtime.h>
#include <cuda_bf16.h>
#include <math.h>

#define Bc   8
#define Lc   256
#define Dc   128
#define Hc   4
#define HDc  32
#define NROW (Bc*Lc)      // 2048
#define RQ   8            // rows per block in qkv GEMM
#define RF   4            // rows per block in ffn
#define NTAU 257
#define DQR  1028         // floats per g_dqt row: 4 heads * 257 taus
#define CVTB 129          // blocks for timeV bf16 conversion

#define TQ2  4            // queries per attention block
#define CH   64           // key chunk (pass 1 staging)
#define PADK 132          // floats per padded smem row (33 float4)
#define NEGV (-4294967295.0f)
#define SCALE 0.17677669529663689f
// dyn smem floats: sKV 8448 + sQ 512 + sS 4096 = 13056; ints: tm 1024
#define SMEM_ATTN (13056*4 + 1024*4)

// ---------------- device scratch ----------------
__device__ __align__(16) float g_seqs[NROW*Dc];
__device__ __align__(16) float g_qin [NROW*Dc];
__device__ __align__(16) float g_Q   [NROW*Dc];   // pre-scaled by 1/sqrt(HD)
__device__ __align__(16) float g_Kc  [NROW*Dc];   // K + bk + posK
__device__ __align__(16) float g_Vc  [NROW*Dc];   // V + bv + posV
__device__ __align__(16) float g_dqt [NROW*DQR];  // [row][h][tau]
__device__ __align__(16) __nv_bfloat16 g_tVb[NTAU*Dc]; // bf16 copy of timeV

// ---------------- K0: embedding + LN1(layer 0); tail blocks convert timeV ----------------
__global__ void __launch_bounds__(128) k_embed(const int* __restrict__ log_seqs,
                        const float* __restrict__ item_emb,
                        const float* __restrict__ g1, const float* __restrict__ b1,
                        const float* __restrict__ timeV) {
    __shared__ float r1[4], r2[4];
    int row = blockIdx.x, t = threadIdx.x;
    if (row >= NROW) { // timeV bf16 conversion tail
        int i = (row - NROW)*256 + t*2;
        if (i < NTAU*Dc) {
            float2 v = *(const float2*)&timeV[i];
            *(__nv_bfloat162*)&g_tVb[i] = __floats2bfloat162_rn(v.x, v.y);
        }
        return;
    }
    int warp = t >> 5, lane = t & 31;
    int idx = log_seqs[row];
    float v = (idx == 0) ? 0.f
                         : item_emb[idx*Dc + t] * 11.313708498984761f; // sqrt(128)
    g_seqs[row*Dc + t] = v;
    float s = v, ss = v*v;
    #pragma unroll
    for (int o = 16; o >= 1; o >>= 1) {
        s  += __shfl_xor_sync(0xffffffffu, s,  o);
        ss += __shfl_xor_sync(0xffffffffu, ss, o);
    }
    if (lane == 0) { r1[warp] = s; r2[warp] = ss; }
    __syncthreads();
    float tot  = r1[0]+r1[1]+r1[2]+r1[3];
    float tots = r2[0]+r2[1]+r2[2]+r2[3];
    float m = tot * (1.f/Dc);
    float inv = rsqrtf(tots * (1.f/Dc) - m*m + 1e-8f);
    g_qin[row*Dc + t] = (v - m) * inv * g1[t] + b1[t];
}

// ---------------- K1: QKV projections (blockIdx.y selects matrix) ----------------
__global__ void __launch_bounds__(128) k_qkv(
                      const float* __restrict__ Wq, const float* __restrict__ Wk,
                      const float* __restrict__ Wv,
                      const float* __restrict__ bq, const float* __restrict__ bk,
                      const float* __restrict__ bv,
                      const float* __restrict__ posK, const float* __restrict__ posV) {
    __shared__ __align__(16) float s_x[RQ][Dc];
    int t = threadIdx.x;
    int mat = blockIdx.y;
    int row0 = blockIdx.x * RQ;

    const float* X = (mat == 0) ? g_qin : g_seqs;
    const float* W = (mat == 0) ? Wq : (mat == 1) ? Wk : Wv;
    const float* B = (mat == 0) ? bq : (mat == 1) ? bk : bv;
    float*       O = (mat == 0) ? g_Q : (mat == 1) ? g_Kc : g_Vc;
    const float* P = (mat == 1) ? posK : posV;

    for (int i = t; i < RQ*Dc; i += 128)
        ((float*)s_x)[i] = X[row0*Dc + i];
    __syncthreads();

    float acc[RQ];
    #pragma unroll
    for (int r = 0; r < RQ; ++r) acc[r] = 0.f;

    for (int k = 0; k < Dc; k += 4) {
        float w0 = W[(k+0)*Dc + t], w1 = W[(k+1)*Dc + t];
        float w2 = W[(k+2)*Dc + t], w3 = W[(k+3)*Dc + t];
        #pragma unroll
        for (int r = 0; r < RQ; ++r) {
            float4 x = *(const float4*)&s_x[r][k];
            acc[r] = fmaf(x.x,w0, fmaf(x.y,w1, fmaf(x.z,w2, fmaf(x.w,w3, acc[r]))));
        }
    }

    float bb = B[t];
    #pragma unroll
    for (int r = 0; r < RQ; ++r) {
        int row = row0 + r;
        if (mat == 0) {
            O[row*Dc + t] = (acc[r] + bb) * SCALE;   // fold 1/sqrt(HD) into Q
        } else {
            O[row*Dc + t] = acc[r] + bb + P[(row & (Lc-1))*Dc + t];
        }
    }
}

// ---------------- K1c: dqt[row][h][tau] = Qs[row,h,:] . timeK[tau,h,:] ----------------
#define QTROWS 16
__global__ void __launch_bounds__(256, 4) k_qt(const float* __restrict__ timeK) {
    __shared__ __align__(16) float sQ[QTROWS*128];   // 8 KB
    int t = threadIdx.x;
    int w = t >> 5, lane = t & 31;
    int h = w & 3;
    int tau = blockIdx.y*64 + (w >> 2)*32 + lane;
    int r0 = blockIdx.x * QTROWS;
    bool valid = (tau < NTAU);

    float4 tr[8];
    if (valid) {
        const float4* src = (const float4*)&timeK[tau*128 + h*32];
        #pragma unroll
        for (int j = 0; j < 8; ++j) tr[j] = src[j];
    }

    { // stage 16 Q rows (coalesced): 512 float4
        const float4* src = (const float4*)&g_Q[r0*128];
        float4* dst = (float4*)sQ;
        dst[t] = src[t];
        dst[t + 256] = src[t + 256];
    }
    __syncthreads();
    if (valid) {
        for (int r = 0; r < QTROWS; r += 2) {
            const float4* qa = (const float4*)&sQ[r*128 + h*32];       // broadcast
            const float4* qb = (const float4*)&sQ[(r+1)*128 + h*32];   // broadcast
            float a0 = 0.f, a1 = 0.f, b0 = 0.f, b1 = 0.f;
            #pragma unroll
            for (int j = 0; j < 8; j += 2) {
                float4 qa0 = qa[j], qa1 = qa[j+1];
                float4 qb0 = qb[j], qb1 = qb[j+1];
                a0 += tr[j  ].x*qa0.x + tr[j  ].y*qa0.y + tr[j  ].z*qa0.z + tr[j  ].w*qa0.w;
                a1 += tr[j+1].x*qa1.x + tr[j+1].y*qa1.y + tr[j+1].z*qa1.z + tr[j+1].w*qa1.w;
                b0 += tr[j  ].x*qb0.x + tr[j  ].y*qb0.y + tr[j  ].z*qb0.z + tr[j  ].w*qb0.w;
                b1 += tr[j+1].x*qb1.x + tr[j+1].y*qb1.y + tr[j+1].z*qb1.z + tr[j+1].w*qb1.w;
            }
            g_dqt[(size_t)(r0 + r    )*DQR + h*NTAU + tau] = a0 + a1;   // coalesced
            g_dqt[(size_t)(r0 + r + 1)*DQR + h*NTAU + tau] = b0 + b1;
        }
    }
}

// ---------------- K2: tiled attention, 512 threads ----------------
// Pass 1 splits heads across t>>8; pass 3 splits k interleaved across t>>8
// with an smem reduction (reusing sKV). Pad rows handled downstream by k_ffn.
__global__ void __launch_bounds__(512) k_attn(const int* __restrict__ time_mat) {
    extern __shared__ __align__(16) char smem_raw[];
    float* sKV = (float*)smem_raw;                 // CH*PADK = 8448 (pass1 staging; pass3 reduction)
    float* sQ  = sKV + 8448;                       // TQ2*128 = 512
    float* sS  = sQ  + 512;                        // TQ2*4*256 = 4096
    int*   s_tm = (int*)(sS + 4096);               // TQ2*256 = 1024

    int t = threadIdx.x;                           // 512
    int b  = blockIdx.x >> 6;
    int q0 = (blockIdx.x & 63) * TQ2;
    int row0 = b*Lc + q0;
    int brow = b*Lc;

    { // Q tile: 128 float4
        if (t < 128) {
            const float4* src = (const float4*)&g_Q[row0*128];
            ((float4*)sQ)[t] = src[t];
        }
    }
    { // tm tile: 256 int4
        if (t < 256) {
            const int4* src = (const int4*)&time_mat[row0*256];
            ((int4*)s_tm)[t] = src[t];
        }
    }
    { // init sS = NEGV: 1024 float4
        float4 negv = make_float4(NEGV, NEGV, NEGV, NEGV);
        float4* p = (float4*)sS;
        p[t] = negv;
        p[t + 512] = negv;
    }
    __syncthreads();

    int nkt = ((q0 + TQ2 - 1) >> 6) + 1;

    // ---- pass 1: scores; thread = (hh, q, kl); 2 heads per thread ----
    {
        int q  = (t >> 6) & 3;
        int kl = t & 63;
        int hh = t >> 8;                            // 0 or 1 (head pair)
        const float* dqp = &g_dqt[(size_t)(row0 + q)*DQR + (size_t)hh*2*NTAU];
        for (int kt = 0; kt < nkt; ++kt) {
            int k0 = kt * CH;
            { // coalesced load Kc chunk: 2048 float4, 4 per thread
                const float4* src = (const float4*)&g_Kc[(brow + k0)*128];
                float4* dst = (float4*)sKV;
                #pragma unroll
                for (int j = 0; j < 4; ++j) {
                    int f4 = t + 512*j;
                    dst[(f4 >> 5)*33 + (f4 & 31)] = src[f4];
                }
            }
            __syncthreads();
            int kg = k0 + kl;
            if (kg <= q0 + q) {
                const float4* kr = (const float4*)&sKV[kl*PADK + hh*64];
                const float4* qr = (const float4*)&sQ[q*128 + hh*64];   // broadcast
                float s0 = 0.f, s1 = 0.f;
                #pragma unroll
                for (int j = 0; j < 8; ++j) {
                    float4 kv = kr[j], qv = qr[j];
                    s0 += kv.x*qv.x + kv.y*qv.y + kv.z*qv.z + kv.w*qv.w;
                }
                #pragma unroll
                for (int j = 8; j < 16; ++j) {
                    float4 kv = kr[j], qv = qr[j];
                    s1 += kv.x*qv.x + kv.y*qv.y + kv.z*qv.z + kv.w*qv.w;
                }
                int tau = s_tm[q*256 + kg];
                sS[(q*4 + hh*2 + 0)*256 + kg] = s0 + dqp[tau];
                sS[(q*4 + hh*2 + 1)*256 + kg] = s1 + dqp[NTAU + tau];
            }
            __syncthreads();
        }
    }

    // ---- pass 2: softmax (16 rows of 256; one warp per row) ----
    {
        int w = t >> 5, lane = t & 31;
        float* p = sS + w*256;
        float x[8];
        float mx = -3.4e38f;
        #pragma unroll
        for (int i = 0; i < 8; ++i) { x[i] = p[lane + 32*i]; mx = fmaxf(mx, x[i]); }
        #pragma unroll
        for (int o = 16; o >= 1; o >>= 1)
            mx = fmaxf(mx, __shfl_xor_sync(0xffffffffu, mx, o));
        float s = 0.f;
        #pragma unroll
        for (int i = 0; i < 8; ++i) { x[i] = expf(x[i] - mx); s += x[i]; }
        #pragma unroll
        for (int o = 16; o >= 1; o >>= 1)
            s += __shfl_xor_sync(0xffffffffu, s, o);
        float inv = 1.f / s;
        #pragma unroll
        for (int i = 0; i < 8; ++i) p[lane + 32*i] = x[i] * inv;
    }
    __syncthreads();

    // ---- pass 3: out = A @ (Vc + timeV[bf16]); k split interleaved across halves ----
    {
        int colp = (t & 63) * 2;      // even column
        int q    = (t >> 6) & 3;      // warp-uniform
        int half = t >> 8;            // 0 or 1: k parity
        int h    = colp >> 5;
        int kend = q0 + q + 1;        // exact causal limit
        const float* sA  = sS + (q*4 + h)*256;
        const int*   tmq = s_tm + q*256;
        const float* vbase = &g_Vc[brow*128 + colp];
        float acc0 = 0.f, acc1 = 0.f;
        #pragma unroll 4
        for (int k = half; k < kend; k += 2) {
            float2 v2 = *(const float2*)&vbase[(size_t)k*128];
            float a = sA[k];                               // smem broadcast
            int tau = tmq[k];                              // smem broadcast
            __nv_bfloat162 tv2 = *(const __nv_bfloat162*)&g_tVb[tau*128 + colp];
            float2 tvf = __bfloat1622float2(tv2);
            acc0 = fmaf(a, v2.x + tvf.x, acc0);
            acc1 = fmaf(a, v2.y + tvf.y, acc1);
        }
        // reduce the two k-halves via sKV (idle now)
        sKV[t]       = acc0;
        sKV[1024 + t] = acc1;
        __syncthreads();
        if (t < 256) {
            float r0v = sKV[t]        + sKV[t + 256];
            float r1v = sKV[1024 + t] + sKV[1024 + t + 256];
            int idx = (row0 + q)*128 + colp;
            float2 qi = *(const float2*)&g_qin[idx];
            *(float2*)&g_seqs[idx] = make_float2(qi.x + r0v, qi.y + r1v);
        }
    }
}

// ---------------- K3: LN2 + FFN + residual + pad-mask (+ LN1 of next layer) ----------------
__global__ void __launch_bounds__(128) k_ffn(const int* __restrict__ log_seqs,
                      const float* __restrict__ ln2_g, const float* __restrict__ ln2_b,
                      const float* __restrict__ W1, const float* __restrict__ b1,
                      const float* __restrict__ W2, const float* __restrict__ b2,
                      const float* __restrict__ ng, const float* __restrict__ nb) {
    __shared__ __align__(16) float s_y[RF][Dc];
    __shared__ __align__(16) float s_h[RF][Dc];
    __shared__ float s_mean[RF], s_inv[RF];
    __shared__ int   s_pad[RF];
    int t = threadIdx.x;
    int row0 = blockIdx.x * RF;
    int r = t >> 5, lane = t & 31;

    for (int i = t; i < RF*Dc; i += 128)
        ((float*)s_h)[i] = g_seqs[row0*Dc + i];
    if (t < RF) s_pad[t] = (log_seqs[row0 + t] == 0);
    __syncthreads();

    {
        float4 v4 = *(const float4*)&s_h[r][lane*4];
        float s  = v4.x + v4.y + v4.z + v4.w;
        float ss = v4.x*v4.x + v4.y*v4.y + v4.z*v4.z + v4.w*v4.w;
        #pragma unroll
        for (int o = 16; o >= 1; o >>= 1) {
            s  += __shfl_xor_sync(0xffffffffu, s,  o);
            ss += __shfl_xor_sync(0xffffffffu, ss, o);
        }
        if (lane == 0) {
            float m = s * (1.f/Dc);
            float var = ss * (1.f/Dc) - m*m;
            s_mean[r] = m;
            s_inv[r]  = rsqrtf(var + 1e-8f);
        }
    }
    __syncthreads();

    float g = ln2_g[t], bb = ln2_b[t];
    #pragma unroll
    for (int rr = 0; rr < RF; ++rr)
        s_y[rr][t] = (s_h[rr][t] - s_mean[rr]) * s_inv[rr] * g + bb;
    __syncthreads();

    float a1[RF];
    #pragma unroll
    for (int rr = 0; rr < RF; ++rr) a1[rr] = 0.f;
    for (int k = 0; k < Dc; k += 4) {
        float w0=W1[(k+0)*Dc+t], w1=W1[(k+1)*Dc+t], w2=W1[(k+2)*Dc+t], w3=W1[(k+3)*Dc+t];
        #pragma unroll
        for (int rr = 0; rr < RF; ++rr) {
            float4 y = *(const float4*)&s_y[rr][k];
            a1[rr] = fmaf(y.x,w0, fmaf(y.y,w1, fmaf(y.z,w2, fmaf(y.w,w3, a1[rr]))));
        }
    }
    float b1v = b1[t];
    __syncthreads();
    #pragma unroll
    for (int rr = 0; rr < RF; ++rr)
        s_h[rr][t] = fmaxf(a1[rr] + b1v, 0.f);
    __syncthreads();

    float a2[RF];
    #pragma unroll
    for (int rr = 0; rr < RF; ++rr) a2[rr] = 0.f;
    for (int k = 0; k < Dc; k += 4) {
        float w0=W2[(k+0)*Dc+t], w1=W2[(k+1)*Dc+t], w2=W2[(k+2)*Dc+t], w3=W2[(k+3)*Dc+t];
        #pragma unroll
        for (int rr = 0; rr < RF; ++rr) {
            float4 h4 = *(const float4*)&s_h[rr][k];
            a2[rr] = fmaf(h4.x,w0, fmaf(h4.y,w1, fmaf(h4.z,w2, fmaf(h4.w,w3, a2[rr]))));
        }
    }
    float b2v = b2[t];
    float vout[RF];
    #pragma unroll
    for (int rr = 0; rr < RF; ++rr) {
        vout[rr] = s_pad[rr] ? 0.f : (s_y[rr][t] + a2[rr] + b2v);
        g_seqs[(row0 + rr)*Dc + t] = vout[rr];
    }

    if (ng) {  // LN1 of next layer, fused
        __syncthreads();
        #pragma unroll
        for (int rr = 0; rr < RF; ++rr) s_h[rr][t] = vout[rr];
        __syncthreads();
        {
            float4 v4 = *(const float4*)&s_h[r][lane*4];
            float s  = v4.x + v4.y + v4.z + v4.w;
            float ss = v4.x*v4.x + v4.y*v4.y + v4.z*v4.z + v4.w*v4.w;
            #pragma unroll
            for (int o = 16; o >= 1; o >>= 1) {
                s  += __shfl_xor_sync(0xffffffffu, s,  o);
                ss += __shfl_xor_sync(0xffffffffu, ss, o);
            }
            if (lane == 0) {
                float m = s * (1.f/Dc);
                float var = ss * (1.f/Dc) - m*m;
                s_mean[r] = m;
                s_inv[r]  = rsqrtf(var + 1e-8f);
            }
        }
        __syncthreads();
        float gg = ng[t], bb2 = nb[t];
        #pragma unroll
        for (int rr = 0; rr < RF; ++rr)
            g_qin[(row0 + rr)*Dc + t] = (s_h[rr][t] - s_mean[rr]) * s_inv[rr] * gg + bb2;
    }
}

// ---------------- K4: final LN + pos/neg logits ----------------
__global__ void __launch_bounds__(128) k_logits(
                         const int* __restrict__ pos_seqs, const int* __restrict__ neg_seqs,
                         const float* __restrict__ item_emb,
                         const float* __restrict__ lnf_g, const float* __restrict__ lnf_b,
                         float* __restrict__ out) {
    __shared__ float r1[4], r2[4];
    int row = blockIdx.x, t = threadIdx.x;
    int warp = t >> 5, lane = t & 31;

    float x = g_seqs[row*Dc + t];
    float s = x, ss = x*x;
    #pragma unroll
    for (int o = 16; o >= 1; o >>= 1) {
        s  += __shfl_xor_sync(0xffffffffu, s,  o);
        ss += __shfl_xor_sync(0xffffffffu, ss, o);
    }
    if (lane == 0) { r1[warp] = s; r2[warp] = ss; }
    __syncthreads();
    float tot  = r1[0]+r1[1]+r1[2]+r1[3];
    float tots = r2[0]+r2[1]+r2[2]+r2[3];
    float m = tot * (1.f/Dc);
    float inv = rsqrtf(tots * (1.f/Dc) - m*m + 1e-8f);
    float f = (x - m) * inv * lnf_g[t] + lnf_b[t];

    int pi = pos_seqs[row], ni = neg_seqs[row];
    float pp = f * item_emb[pi*Dc + t];
    float nn = f * item_emb[ni*Dc + t];
    #pragma unroll
    for (int o = 16; o >= 1; o >>= 1) {
        pp += __shfl_xor_sync(0xffffffffu, pp, o);
        nn += __shfl_xor_sync(0xffffffffu, nn, o);
    }
    __syncthreads();
    if (lane == 0) { r1[warp] = pp; r2[warp] = nn; }
    __syncthreads();
    if (t == 0) {
        out[row]        = r1[0]+r1[1]+r1[2]+r1[3];
        out[NROW + row] = r2[0]+r2[1]+r2[2]+r2[3];
    }
}

// ---------------- launch ----------------
extern "C" void kernel_launch(void* const* d_in, const int* in_sizes, int n_in,
                              void* d_out, int out_size) {
    const int*   log_seqs = (const int*)  d_in[1];
    const int*   time_mat = (const int*)  d_in[2];
    const int*   pos_seqs = (const int*)  d_in[3];
    const int*   neg_seqs = (const int*)  d_in[4];
    const float* item_emb = (const float*)d_in[5];
    const float* posK     = (const float*)d_in[6];
    const float* posV     = (const float*)d_in[7];
    const float* timeK    = (const float*)d_in[8];
    const float* timeV    = (const float*)d_in[9];
    const float* ln1_g    = (const float*)d_in[10];
    const float* ln1_b    = (const float*)d_in[11];
    const float* Wq       = (const float*)d_in[12];
    const float* bq       = (const float*)d_in[13];
    const float* Wk       = (const float*)d_in[14];
    const float* bk       = (const float*)d_in[15];
    const float* Wv       = (const float*)d_in[16];
    const float* bv       = (const float*)d_in[17];
    const float* ln2_g    = (const float*)d_in[18];
    const float* ln2_b    = (const float*)d_in[19];
    const float* W1       = (const float*)d_in[20];
    const float* b1       = (const float*)d_in[21];
    const float* W2       = (const float*)d_in[22];
    const float* b2       = (const float*)d_in[23];
    const float* lnf_g    = (const float*)d_in[24];
    const float* lnf_b    = (const float*)d_in[25];
    float* out = (float*)d_out;

    cudaFuncSetAttribute(k_attn, cudaFuncAttributeMaxDynamicSharedMemorySize, SMEM_ATTN);

    k_embed<<<NROW + CVTB, 128>>>(log_seqs, item_emb, ln1_g, ln1_b, timeV);
    for (int i = 0; i < 2; ++i) {
        dim3 gq(NROW/RQ, 3);
        k_qkv<<<gq, 128>>>(Wq + i*Dc*Dc, Wk + i*Dc*Dc, Wv + i*Dc*Dc,
                           bq + i*Dc, bk + i*Dc, bv + i*Dc, posK, posV);
        dim3 gt(NROW/QTROWS, 5);          // (128, 5) = 640 blocks
        k_qt<<<gt, 256>>>(timeK);
        k_attn<<<NROW/TQ2, 512, SMEM_ATTN>>>(time_mat);
        const float* ng = (i == 0) ? (ln1_g + Dc) : nullptr;
        const float* nb = (i == 0) ? (ln1_b + Dc) : nullptr;
        k_ffn<<<NROW/RF, 128>>>(log_seqs, ln2_g + i*Dc, ln2_b + i*Dc,
                                W1 + i*Dc*Dc, b1 + i*Dc,
                                W2 + i*Dc*Dc, b2 + i*Dc, ng, nb);
    }
    k_logits<<<NROW, 128>>>(pos_seqs, neg_seqs, item_emb, lnf_g, lnf_b, out);
}

// round 15
// speedup vs baseline: 1.0604x; 1.0604x over previous
#include <cuda_runtime.h>
#include <cuda_bf16.h>
#include <math.h>

#define Bc   8
#define Lc   256
#define Dc   128
#define Hc   4
#define HDc  32
#define NROW (Bc*Lc)      // 2048
#define RQ   8            // rows per block in qkv GEMM
#define RF   4            // rows per block in ffn
#define NTAU 257
#define DQR  1028         // floats per g_dqt row: 4 heads * 257 taus
#define CVTB 129          // blocks for timeV bf16 conversion

#define TQ2  4            // queries per attention block
#define CH   64           // key chunk (pass 1 staging)
#define PADK 132          // floats per padded smem row (33 float4)
#define NEGV (-4294967295.0f)
#define SCALE 0.17677669529663689f
// dyn smem floats: sKV 8448 + sQ 512 + sS 4096 = 13056; ints: tm 1024
#define SMEM_ATTN (13056*4 + 1024*4)

// ---------------- device scratch ----------------
__device__ __align__(16) float g_seqs[NROW*Dc];
__device__ __align__(16) float g_qin [NROW*Dc];
__device__ __align__(16) float g_Q   [NROW*Dc];   // pre-scaled by 1/sqrt(HD)
__device__ __align__(16) float g_Kc  [NROW*Dc];   // K + bk + posK
__device__ __align__(16) float g_Vc  [NROW*Dc];   // V + bv + posV
__device__ __align__(16) float g_dqt [NROW*DQR];  // [row][h][tau]
__device__ __align__(16) __nv_bfloat16 g_tVb[NTAU*Dc]; // bf16 copy of timeV

// ---------------- K0: embedding + LN1(layer 0); tail blocks convert timeV ----------------
__global__ void __launch_bounds__(128) k_embed(const int* __restrict__ log_seqs,
                        const float* __restrict__ item_emb,
                        const float* __restrict__ g1, const float* __restrict__ b1,
                        const float* __restrict__ timeV) {
    __shared__ float r1[4], r2[4];
    int row = blockIdx.x, t = threadIdx.x;
    if (row >= NROW) { // timeV bf16 conversion tail
        int i = (row - NROW)*256 + t*2;
        if (i < NTAU*Dc) {
            float2 v = *(const float2*)&timeV[i];
            *(__nv_bfloat162*)&g_tVb[i] = __floats2bfloat162_rn(v.x, v.y);
        }
        return;
    }
    int warp = t >> 5, lane = t & 31;
    int idx = log_seqs[row];
    float v = (idx == 0) ? 0.f
                         : item_emb[idx*Dc + t] * 11.313708498984761f; // sqrt(128)
    g_seqs[row*Dc + t] = v;
    float s = v, ss = v*v;
    #pragma unroll
    for (int o = 16; o >= 1; o >>= 1) {
        s  += __shfl_xor_sync(0xffffffffu, s,  o);
        ss += __shfl_xor_sync(0xffffffffu, ss, o);
    }
    if (lane == 0) { r1[warp] = s; r2[warp] = ss; }
    __syncthreads();
    float tot  = r1[0]+r1[1]+r1[2]+r1[3];
    float tots = r2[0]+r2[1]+r2[2]+r2[3];
    float m = tot * (1.f/Dc);
    float inv = rsqrtf(tots * (1.f/Dc) - m*m + 1e-8f);
    g_qin[row*Dc + t] = (v - m) * inv * g1[t] + b1[t];
}

// ---------------- K1: QKV projections (blockIdx.y selects matrix) ----------------
__global__ void __launch_bounds__(128) k_qkv(
                      const float* __restrict__ Wq, const float* __restrict__ Wk,
                      const float* __restrict__ Wv,
                      const float* __restrict__ bq, const float* __restrict__ bk,
                      const float* __restrict__ bv,
                      const float* __restrict__ posK, const float* __restrict__ posV) {
    __shared__ __align__(16) float s_x[RQ][Dc];
    int t = threadIdx.x;
    int mat = blockIdx.y;
    int row0 = blockIdx.x * RQ;

    const float* X = (mat == 0) ? g_qin : g_seqs;
    const float* W = (mat == 0) ? Wq : (mat == 1) ? Wk : Wv;
    const float* B = (mat == 0) ? bq : (mat == 1) ? bk : bv;
    float*       O = (mat == 0) ? g_Q : (mat == 1) ? g_Kc : g_Vc;
    const float* P = (mat == 1) ? posK : posV;

    for (int i = t; i < RQ*Dc; i += 128)
        ((float*)s_x)[i] = X[row0*Dc + i];
    __syncthreads();

    float acc[RQ];
    #pragma unroll
    for (int r = 0; r < RQ; ++r) acc[r] = 0.f;

    for (int k = 0; k < Dc; k += 4) {
        float w0 = W[(k+0)*Dc + t], w1 = W[(k+1)*Dc + t];
        float w2 = W[(k+2)*Dc + t], w3 = W[(k+3)*Dc + t];
        #pragma unroll
        for (int r = 0; r < RQ; ++r) {
            float4 x = *(const float4*)&s_x[r][k];
            acc[r] = fmaf(x.x,w0, fmaf(x.y,w1, fmaf(x.z,w2, fmaf(x.w,w3, acc[r]))));
        }
    }

    float bb = B[t];
    #pragma unroll
    for (int r = 0; r < RQ; ++r) {
        int row = row0 + r;
        if (mat == 0) {
            O[row*Dc + t] = (acc[r] + bb) * SCALE;   // fold 1/sqrt(HD) into Q
        } else {
            O[row*Dc + t] = acc[r] + bb + P[(row & (Lc-1))*Dc + t];
        }
    }
}

// ---------------- K1c: dqt[row][h][tau] = Qs[row,h,:] . timeK[tau,h,:] ----------------
#define QTROWS 16
__global__ void __launch_bounds__(256, 4) k_qt(const float* __restrict__ timeK) {
    __shared__ __align__(16) float sQ[QTROWS*128];   // 8 KB
    int t = threadIdx.x;
    int w = t >> 5, lane = t & 31;
    int h = w & 3;
    int tau = blockIdx.y*64 + (w >> 2)*32 + lane;
    int r0 = blockIdx.x * QTROWS;
    bool valid = (tau < NTAU);

    float4 tr[8];
    if (valid) {
        const float4* src = (const float4*)&timeK[tau*128 + h*32];
        #pragma unroll
        for (int j = 0; j < 8; ++j) tr[j] = src[j];
    }

    { // stage 16 Q rows (coalesced): 512 float4
        const float4* src = (const float4*)&g_Q[r0*128];
        float4* dst = (float4*)sQ;
        dst[t] = src[t];
        dst[t + 256] = src[t + 256];
    }
    __syncthreads();
    if (valid) {
        for (int r = 0; r < QTROWS; r += 2) {
            const float4* qa = (const float4*)&sQ[r*128 + h*32];       // broadcast
            const float4* qb = (const float4*)&sQ[(r+1)*128 + h*32];   // broadcast
            float a0 = 0.f, a1 = 0.f, b0 = 0.f, b1 = 0.f;
            #pragma unroll
            for (int j = 0; j < 8; j += 2) {
                float4 qa0 = qa[j], qa1 = qa[j+1];
                float4 qb0 = qb[j], qb1 = qb[j+1];
                a0 += tr[j  ].x*qa0.x + tr[j  ].y*qa0.y + tr[j  ].z*qa0.z + tr[j  ].w*qa0.w;
                a1 += tr[j+1].x*qa1.x + tr[j+1].y*qa1.y + tr[j+1].z*qa1.z + tr[j+1].w*qa1.w;
                b0 += tr[j  ].x*qb0.x + tr[j  ].y*qb0.y + tr[j  ].z*qb0.z + tr[j  ].w*qb0.w;
                b1 += tr[j+1].x*qb1.x + tr[j+1].y*qb1.y + tr[j+1].z*qb1.z + tr[j+1].w*qb1.w;
            }
            g_dqt[(size_t)(r0 + r    )*DQR + h*NTAU + tau] = a0 + a1;   // coalesced
            g_dqt[(size_t)(r0 + r + 1)*DQR + h*NTAU + tau] = b0 + b1;
        }
    }
}

// ---------------- K2: tiled attention, 512 threads ----------------
// Pass 1 splits heads across t>>8; pass 3: 4 cols/thread + 4-way k split
// (halves LSU ops per output) with float4 reduction through sKV.
__global__ void __launch_bounds__(512, 4) k_attn(const int* __restrict__ time_mat) {
    extern __shared__ __align__(16) char smem_raw[];
    float* sKV = (float*)smem_raw;                 // CH*PADK = 8448 (pass1 staging; pass3 reduction)
    float* sQ  = sKV + 8448;                       // TQ2*128 = 512
    float* sS  = sQ  + 512;                        // TQ2*4*256 = 4096
    int*   s_tm = (int*)(sS + 4096);               // TQ2*256 = 1024

    int t = threadIdx.x;                           // 512
    int b  = blockIdx.x >> 6;
    int q0 = (blockIdx.x & 63) * TQ2;
    int row0 = b*Lc + q0;
    int brow = b*Lc;

    { // Q tile: 128 float4
        if (t < 128) {
            const float4* src = (const float4*)&g_Q[row0*128];
            ((float4*)sQ)[t] = src[t];
        }
    }
    { // tm tile: 256 int4
        if (t < 256) {
            const int4* src = (const int4*)&time_mat[row0*256];
            ((int4*)s_tm)[t] = src[t];
        }
    }
    { // init sS = NEGV: 1024 float4
        float4 negv = make_float4(NEGV, NEGV, NEGV, NEGV);
        float4* p = (float4*)sS;
        p[t] = negv;
        p[t + 512] = negv;
    }
    __syncthreads();

    int nkt = ((q0 + TQ2 - 1) >> 6) + 1;

    // ---- pass 1: scores; thread = (hh, q, kl); 2 heads per thread ----
    {
        int q  = (t >> 6) & 3;
        int kl = t & 63;
        int hh = t >> 8;                            // 0 or 1 (head pair)
        const float* dqp = &g_dqt[(size_t)(row0 + q)*DQR + (size_t)hh*2*NTAU];
        for (int kt = 0; kt < nkt; ++kt) {
            int k0 = kt * CH;
            { // coalesced load Kc chunk: 2048 float4, 4 per thread
                const float4* src = (const float4*)&g_Kc[(brow + k0)*128];
                float4* dst = (float4*)sKV;
                #pragma unroll
                for (int j = 0; j < 4; ++j) {
                    int f4 = t + 512*j;
                    dst[(f4 >> 5)*33 + (f4 & 31)] = src[f4];
                }
            }
            __syncthreads();
            int kg = k0 + kl;
            if (kg <= q0 + q) {
                const float4* kr = (const float4*)&sKV[kl*PADK + hh*64];
                const float4* qr = (const float4*)&sQ[q*128 + hh*64];   // broadcast
                float s0 = 0.f, s1 = 0.f;
                #pragma unroll
                for (int j = 0; j < 8; ++j) {
                    float4 kv = kr[j], qv = qr[j];
                    s0 += kv.x*qv.x + kv.y*qv.y + kv.z*qv.z + kv.w*qv.w;
                }
                #pragma unroll
                for (int j = 8; j < 16; ++j) {
                    float4 kv = kr[j], qv = qr[j];
                    s1 += kv.x*qv.x + kv.y*qv.y + kv.z*qv.z + kv.w*qv.w;
                }
                int tau = s_tm[q*256 + kg];
                sS[(q*4 + hh*2 + 0)*256 + kg] = s0 + dqp[tau];
                sS[(q*4 + hh*2 + 1)*256 + kg] = s1 + dqp[NTAU + tau];
            }
            __syncthreads();
        }
    }

    // ---- pass 2: softmax (16 rows of 256; one warp per row) ----
    {
        int w = t >> 5, lane = t & 31;
        float* p = sS + w*256;
        float x[8];
        float mx = -3.4e38f;
        #pragma unroll
        for (int i = 0; i < 8; ++i) { x[i] = p[lane + 32*i]; mx = fmaxf(mx, x[i]); }
        #pragma unroll
        for (int o = 16; o >= 1; o >>= 1)
            mx = fmaxf(mx, __shfl_xor_sync(0xffffffffu, mx, o));
        float s = 0.f;
        #pragma unroll
        for (int i = 0; i < 8; ++i) { x[i] = expf(x[i] - mx); s += x[i]; }
        #pragma unroll
        for (int o = 16; o >= 1; o >>= 1)
            s += __shfl_xor_sync(0xffffffffu, s, o);
        float inv = 1.f / s;
        #pragma unroll
        for (int i = 0; i < 8; ++i) p[lane + 32*i] = x[i] * inv;
    }
    __syncthreads();

    // ---- pass 3: out = A @ (Vc + timeV[bf16]); 4 cols/thread, 4-way k split ----
    {
        int q       = t >> 7;          // 0..3
        int quarter = (t >> 5) & 3;    // 0..3: k residue class
        int colg    = t & 31;
        int col     = colg * 4;
        int h       = colg >> 3;       // head = col>>5
        int kend = q0 + q + 1;         // exact causal limit
        const float* sA  = sS + (q*4 + h)*256;
        const int*   tmq = s_tm + q*256;
        const float* vbase = &g_Vc[brow*128 + col];
        float4 acc = make_float4(0.f, 0.f, 0.f, 0.f);
        #pragma unroll 2
        for (int k = quarter; k < kend; k += 4) {
            float4 v4 = *(const float4*)&vbase[(size_t)k*128];   // LDG.128 coalesced
            float a = sA[k];                                      // LDS broadcast
            int tau = tmq[k];                                     // LDS broadcast
            uint2 raw = *(const uint2*)&g_tVb[tau*128 + col];     // LDG.64 (4 bf16)
            __nv_bfloat162 lo = *reinterpret_cast<__nv_bfloat162*>(&raw.x);
            __nv_bfloat162 hi = *reinterpret_cast<__nv_bfloat162*>(&raw.y);
            float2 f0 = __bfloat1622float2(lo);
            float2 f1 = __bfloat1622float2(hi);
            acc.x = fmaf(a, v4.x + f0.x, acc.x);
            acc.y = fmaf(a, v4.y + f0.y, acc.y);
            acc.z = fmaf(a, v4.z + f1.x, acc.z);
            acc.w = fmaf(a, v4.w + f1.y, acc.w);
        }
        *(float4*)&sKV[quarter*512 + q*128 + col] = acc;
        __syncthreads();
        if (t < 128) {
            int qq = t >> 5, cg = (t & 31) * 4;
            int o = qq*128 + cg;
            float4 r0v = *(float4*)&sKV[o];
            float4 r1v = *(float4*)&sKV[512  + o];
            float4 r2v = *(float4*)&sKV[1024 + o];
            float4 r3v = *(float4*)&sKV[1536 + o];
            int idx = (row0 + qq)*128 + cg;
            float4 qi = *(const float4*)&g_qin[idx];
            float4 ov;
            ov.x = qi.x + ((r0v.x + r1v.x) + (r2v.x + r3v.x));
            ov.y = qi.y + ((r0v.y + r1v.y) + (r2v.y + r3v.y));
            ov.z = qi.z + ((r0v.z + r1v.z) + (r2v.z + r3v.z));
            ov.w = qi.w + ((r0v.w + r1v.w) + (r2v.w + r3v.w));
            *(float4*)&g_seqs[idx] = ov;
        }
    }
}

// ---------------- K3: LN2 + FFN + residual + pad-mask (+ LN1 of next layer) ----------------
__global__ void __launch_bounds__(128) k_ffn(const int* __restrict__ log_seqs,
                      const float* __restrict__ ln2_g, const float* __restrict__ ln2_b,
                      const float* __restrict__ W1, const float* __restrict__ b1,
                      const float* __restrict__ W2, const float* __restrict__ b2,
                      const float* __restrict__ ng, const float* __restrict__ nb) {
    __shared__ __align__(16) float s_y[RF][Dc];
    __shared__ __align__(16) float s_h[RF][Dc];
    __shared__ float s_mean[RF], s_inv[RF];
    __shared__ int   s_pad[RF];
    int t = threadIdx.x;
    int row0 = blockIdx.x * RF;
    int r = t >> 5, lane = t & 31;

    for (int i = t; i < RF*Dc; i += 128)
        ((float*)s_h)[i] = g_seqs[row0*Dc + i];
    if (t < RF) s_pad[t] = (log_seqs[row0 + t] == 0);
    __syncthreads();

    {
        float4 v4 = *(const float4*)&s_h[r][lane*4];
        float s  = v4.x + v4.y + v4.z + v4.w;
        float ss = v4.x*v4.x + v4.y*v4.y + v4.z*v4.z + v4.w*v4.w;
        #pragma unroll
        for (int o = 16; o >= 1; o >>= 1) {
            s  += __shfl_xor_sync(0xffffffffu, s,  o);
            ss += __shfl_xor_sync(0xffffffffu, ss, o);
        }
        if (lane == 0) {
            float m = s * (1.f/Dc);
            float var = ss * (1.f/Dc) - m*m;
            s_mean[r] = m;
            s_inv[r]  = rsqrtf(var + 1e-8f);
        }
    }
    __syncthreads();

    float g = ln2_g[t], bb = ln2_b[t];
    #pragma unroll
    for (int rr = 0; rr < RF; ++rr)
        s_y[rr][t] = (s_h[rr][t] - s_mean[rr]) * s_inv[rr] * g + bb;
    __syncthreads();

    float a1[RF];
    #pragma unroll
    for (int rr = 0; rr < RF; ++rr) a1[rr] = 0.f;
    for (int k = 0; k < Dc; k += 4) {
        float w0=W1[(k+0)*Dc+t], w1=W1[(k+1)*Dc+t], w2=W1[(k+2)*Dc+t], w3=W1[(k+3)*Dc+t];
        #pragma unroll
        for (int rr = 0; rr < RF; ++rr) {
            float4 y = *(const float4*)&s_y[rr][k];
            a1[rr] = fmaf(y.x,w0, fmaf(y.y,w1, fmaf(y.z,w2, fmaf(y.w,w3, a1[rr]))));
        }
    }
    float b1v = b1[t];
    __syncthreads();
    #pragma unroll
    for (int rr = 0; rr < RF; ++rr)
        s_h[rr][t] = fmaxf(a1[rr] + b1v, 0.f);
    __syncthreads();

    float a2[RF];
    #pragma unroll
    for (int rr = 0; rr < RF; ++rr) a2[rr] = 0.f;
    for (int k = 0; k < Dc; k += 4) {
        float w0=W2[(k+0)*Dc+t], w1=W2[(k+1)*Dc+t], w2=W2[(k+2)*Dc+t], w3=W2[(k+3)*Dc+t];
        #pragma unroll
        for (int rr = 0; rr < RF; ++rr) {
            float4 h4 = *(const float4*)&s_h[rr][k];
            a2[rr] = fmaf(h4.x,w0, fmaf(h4.y,w1, fmaf(h4.z,w2, fmaf(h4.w,w3, a2[rr]))));
        }
    }
    float b2v = b2[t];
    float vout[RF];
    #pragma unroll
    for (int rr = 0; rr < RF; ++rr) {
        vout[rr] = s_pad[rr] ? 0.f : (s_y[rr][t] + a2[rr] + b2v);
        g_seqs[(row0 + rr)*Dc + t] = vout[rr];
    }

    if (ng) {  // LN1 of next layer, fused
        __syncthreads();
        #pragma unroll
        for (int rr = 0; rr < RF; ++rr) s_h[rr][t] = vout[rr];
        __syncthreads();
        {
            float4 v4 = *(const float4*)&s_h[r][lane*4];
            float s  = v4.x + v4.y + v4.z + v4.w;
            float ss = v4.x*v4.x + v4.y*v4.y + v4.z*v4.z + v4.w*v4.w;
            #pragma unroll
            for (int o = 16; o >= 1; o >>= 1) {
                s  += __shfl_xor_sync(0xffffffffu, s,  o);
                ss += __shfl_xor_sync(0xffffffffu, ss, o);
            }
            if (lane == 0) {
                float m = s * (1.f/Dc);
                float var = ss * (1.f/Dc) - m*m;
                s_mean[r] = m;
                s_inv[r]  = rsqrtf(var + 1e-8f);
            }
        }
        __syncthreads();
        float gg = ng[t], bb2 = nb[t];
        #pragma unroll
        for (int rr = 0; rr < RF; ++rr)
            g_qin[(row0 + rr)*Dc + t] = (s_h[rr][t] - s_mean[rr]) * s_inv[rr] * gg + bb2;
    }
}

// ---------------- K4: final LN + pos/neg logits ----------------
__global__ void __launch_bounds__(128) k_logits(
                         const int* __restrict__ pos_seqs, const int* __restrict__ neg_seqs,
                         const float* __restrict__ item_emb,
                         const float* __restrict__ lnf_g, const float* __restrict__ lnf_b,
                         float* __restrict__ out) {
    __shared__ float r1[4], r2[4];
    int row = blockIdx.x, t = threadIdx.x;
    int warp = t >> 5, lane = t & 31;

    float x = g_seqs[row*Dc + t];
    float s = x, ss = x*x;
    #pragma unroll
    for (int o = 16; o >= 1; o >>= 1) {
        s  += __shfl_xor_sync(0xffffffffu, s,  o);
        ss += __shfl_xor_sync(0xffffffffu, ss, o);
    }
    if (lane == 0) { r1[warp] = s; r2[warp] = ss; }
    __syncthreads();
    float tot  = r1[0]+r1[1]+r1[2]+r1[3];
    float tots = r2[0]+r2[1]+r2[2]+r2[3];
    float m = tot * (1.f/Dc);
    float inv = rsqrtf(tots * (1.f/Dc) - m*m + 1e-8f);
    float f = (x - m) * inv * lnf_g[t] + lnf_b[t];

    int pi = pos_seqs[row], ni = neg_seqs[row];
    float pp = f * item_emb[pi*Dc + t];
    float nn = f * item_emb[ni*Dc + t];
    #pragma unroll
    for (int o = 16; o >= 1; o >>= 1) {
        pp += __shfl_xor_sync(0xffffffffu, pp, o);
        nn += __shfl_xor_sync(0xffffffffu, nn, o);
    }
    __syncthreads();
    if (lane == 0) { r1[warp] = pp; r2[warp] = nn; }
    __syncthreads();
    if (t == 0) {
        out[row]        = r1[0]+r1[1]+r1[2]+r1[3];
        out[NROW + row] = r2[0]+r2[1]+r2[2]+r2[3];
    }
}

// ---------------- launch ----------------
extern "C" void kernel_launch(void* const* d_in, const int* in_sizes, int n_in,
                              void* d_out, int out_size) {
    const int*   log_seqs = (const int*)  d_in[1];
    const int*   time_mat = (const int*)  d_in[2];
    const int*   pos_seqs = (const int*)  d_in[3];
    const int*   neg_seqs = (const int*)  d_in[4];
    const float* item_emb = (const float*)d_in[5];
    const float* posK     = (const float*)d_in[6];
    const float* posV     = (const float*)d_in[7];
    const float* timeK    = (const float*)d_in[8];
    const float* timeV    = (const float*)d_in[9];
    const float* ln1_g    = (const float*)d_in[10];
    const float* ln1_b    = (const float*)d_in[11];
    const float* Wq       = (const float*)d_in[12];
    const float* bq       = (const float*)d_in[13];
    const float* Wk       = (const float*)d_in[14];
    const float* bk       = (const float*)d_in[15];
    const float* Wv       = (const float*)d_in[16];
    const float* bv       = (const float*)d_in[17];
    const float* ln2_g    = (const float*)d_in[18];
    const float* ln2_b    = (const float*)d_in[19];
    const float* W1       = (const float*)d_in[20];
    const float* b1       = (const float*)d_in[21];
    const float* W2       = (const float*)d_in[22];
    const float* b2       = (const float*)d_in[23];
    const float* lnf_g    = (const float*)d_in[24];
    const float* lnf_b    = (const float*)d_in[25];
    float* out = (float*)d_out;

    cudaFuncSetAttribute(k_attn, cudaFuncAttributeMaxDynamicSharedMemorySize, SMEM_ATTN);

    k_embed<<<NROW + CVTB, 128>>>(log_seqs, item_emb, ln1_g, ln1_b, timeV);
    for (int i = 0; i < 2; ++i) {
        dim3 gq(NROW/RQ, 3);
        k_qkv<<<gq, 128>>>(Wq + i*Dc*Dc, Wk + i*Dc*Dc, Wv + i*Dc*Dc,
                           bq + i*Dc, bk + i*Dc, bv + i*Dc, posK, posV);
        dim3 gt(NROW/QTROWS, 5);          // (128, 5) = 640 blocks
        k_qt<<<gt, 256>>>(timeK);
        k_attn<<<NROW/TQ2, 512, SMEM_ATTN>>>(time_mat);
        const float* ng = (i == 0) ? (ln1_g + Dc) : nullptr;
        const float* nb = (i == 0) ? (ln1_b + Dc) : nullptr;
        k_ffn<<<NROW/RF, 128>>>(log_seqs, ln2_g + i*Dc, ln2_b + i*Dc,
                                W1 + i*Dc*Dc, b1 + i*Dc,
                                W2 + i*Dc*Dc, b2 + i*Dc, ng, nb);
    }
    k_logits<<<NROW, 128>>>(pos_seqs, neg_seqs, item_emb, lnf_g, lnf_b, out);
}